// round 6
// baseline (speedup 1.0000x reference)
#include <cuda_runtime.h>
#include <cuda_bf16.h>
#include <stdint.h>

#define TOKENS 8192
#define IN_F   4096
#define OUT_F  4096
#define RNK    16

// ================= device scratch (no allocs allowed) =================
__device__ float g_S[256];
__device__ float g_C[256];
__device__ float g_Qs[256];                         // alpha * Q5
__device__ float g_Aq[RNK * IN_F];                  // (alpha Q5) @ lora_A
__device__ __align__(1024) __nv_bfloat16 g_Xh[(size_t)TOKENS * IN_F];
__device__ __align__(1024) __nv_bfloat16 g_Xl[(size_t)TOKENS * IN_F];
__device__ __align__(1024) __nv_bfloat16 g_Wh[(size_t)OUT_F * IN_F];
__device__ __align__(1024) __nv_bfloat16 g_Wl[(size_t)OUT_F * IN_F];

// ================= K0/K1/K2: alpha*Q5 in rank-16 space (validated) ==========
__global__ void k_zero() { int t = threadIdx.x; g_S[t] = 0.f; g_C[t] = 0.f; }

__global__ void k_sc(const float* __restrict__ lA, const float* __restrict__ lB) {
    int t = threadIdx.x, i = t >> 4, j = t & 15;
    int k0 = blockIdx.x * 256;
    const float4* Ai = (const float4*)(lA + (size_t)i * IN_F);
    const float4* Aj = (const float4*)(lA + (size_t)j * IN_F);
    float s = 0.f;
#pragma unroll 8
    for (int k4 = k0 / 4; k4 < k0 / 4 + 64; k4++) {
        float4 a = Ai[k4], b = Aj[k4];
        s += a.x * b.x + a.y * b.y + a.z * b.z + a.w * b.w;
    }
    float c = 0.f;
#pragma unroll 4
    for (int k = k0; k < k0 + 256; k++)
        c += lB[(size_t)k * RNK + i] * lB[(size_t)k * RNK + j];
    atomicAdd(&g_S[t], s);
    atomicAdd(&g_C[t], c);
}

__global__ void k_ns() {
    __shared__ float S[256], C[256], Q[256], Rm[256], T1[256], T2[256], P[256], W2[256];
    int t = threadIdx.x, i = t >> 4, j = t & 15;
    S[t] = g_S[t]; C[t] = g_C[t];
    __syncthreads();
    W2[t] = S[i * 16 + j] * C[j * 16 + i];
    __syncthreads();
    for (int s = 128; s; s >>= 1) { if (t < s) W2[t] += W2[t + s]; __syncthreads(); }
    float alpha = sqrtf(W2[0]);
    float nrm = alpha + 1e-7f;
    Q[t] = (i == j) ? (1.f / nrm) : 0.f;
    Rm[t] = C[t] / (nrm * nrm);
    __syncthreads();
    const float ca = 3.4445f, cb = -4.775f, cc = 2.0315f;
    for (int step = 0; step < 5; step++) {
        float acc = 0.f;
#pragma unroll
        for (int k = 0; k < 16; k++) acc += S[i * 16 + k] * Rm[k * 16 + j];
        T1[t] = acc; __syncthreads();
        acc = 0.f;
#pragma unroll
        for (int k = 0; k < 16; k++) acc += T1[i * 16 + k] * T1[k * 16 + j];
        T2[t] = acc; __syncthreads();
        P[t] = cc * T2[t] + cb * T1[t] + ((i == j) ? ca : 0.f);
        __syncthreads();
        acc = 0.f;
#pragma unroll
        for (int k = 0; k < 16; k++) acc += Q[i * 16 + k] * P[k * 16 + j];
        W2[t] = acc; __syncthreads(); Q[t] = W2[t];
        acc = 0.f;
#pragma unroll
        for (int k = 0; k < 16; k++) acc += Rm[i * 16 + k] * P[k * 16 + j];
        W2[t] = acc; __syncthreads();
        acc = 0.f;
#pragma unroll
        for (int k = 0; k < 16; k++) acc += P[k * 16 + i] * W2[k * 16 + j];
        T1[t] = acc; __syncthreads(); Rm[t] = T1[t]; __syncthreads();
    }
    g_Qs[t] = alpha * Q[t];
}

// ================= K3: Aq = (alpha Q5) @ lora_A =================
__global__ void k_aq(const float* __restrict__ lA) {
    int j = blockIdx.x * 256 + threadIdx.x;
    float a[16];
#pragma unroll
    for (int s = 0; s < 16; s++) a[s] = lA[(size_t)s * IN_F + j];
#pragma unroll
    for (int r = 0; r < 16; r++) {
        float acc = 0.f;
#pragma unroll
        for (int s = 0; s < 16; s++) acc += g_Qs[r * 16 + s] * a[s];
        g_Aq[(size_t)r * IN_F + j] = acc;
    }
}

// ===== K4 (merged prep): x hi/lo split  AND  W' = W + lB@Aq hi/lo split =====
#define XSPLIT_BLOCKS 32768    // (TOKENS * IN_F / 4) / 256
__global__ void k_prep(const float* __restrict__ x, const float* __restrict__ W,
                       const float* __restrict__ lB) {
    if (blockIdx.x < XSPLIT_BLOCKS) {
        size_t i = (size_t)blockIdx.x * 256 + threadIdx.x;   // float4 index
        float4 v = ((const float4*)x)[i];
        __nv_bfloat16 h0 = __float2bfloat16(v.x), h1 = __float2bfloat16(v.y);
        __nv_bfloat16 h2 = __float2bfloat16(v.z), h3 = __float2bfloat16(v.w);
        __nv_bfloat162 a; a.x = h0; a.y = h1;
        __nv_bfloat162 b; b.x = h2; b.y = h3;
        ((__nv_bfloat162*)g_Xh)[i * 2]     = a;
        ((__nv_bfloat162*)g_Xh)[i * 2 + 1] = b;
        __nv_bfloat162 c, d;
        c.x = __float2bfloat16(v.x - __bfloat162float(h0));
        c.y = __float2bfloat16(v.y - __bfloat162float(h1));
        d.x = __float2bfloat16(v.z - __bfloat162float(h2));
        d.y = __float2bfloat16(v.w - __bfloat162float(h3));
        ((__nv_bfloat162*)g_Xl)[i * 2]     = c;
        ((__nv_bfloat162*)g_Xl)[i * 2 + 1] = d;
        return;
    }
    __shared__ float sAq[16 * 256];
    __shared__ float sB[64 * 16];
    int b = blockIdx.x - XSPLIT_BLOCKS;
    int tid = threadIdx.x;
    int c0 = (b & 15) * 256, i0 = (b >> 4) * 64;
#pragma unroll
    for (int q = 0; q < 16; q++) {
        int i = tid + 256 * q;
        sAq[i] = g_Aq[(size_t)(i >> 8) * IN_F + c0 + (i & 255)];
    }
#pragma unroll
    for (int q = 0; q < 4; q++) {
        int i = tid + 256 * q;
        sB[i] = lB[(size_t)(i0 + (i >> 4)) * RNK + (i & 15)];
    }
    __syncthreads();
    int col = c0 + tid;
    float aq[16];
#pragma unroll
    for (int r = 0; r < 16; r++) aq[r] = sAq[r * 256 + tid];
    for (int ir = 0; ir < 64; ir++) {
        size_t off = (size_t)(i0 + ir) * IN_F + col;
        float acc = W[off];
#pragma unroll
        for (int r = 0; r < 16; r++) acc += sB[ir * 16 + r] * aq[r];
        __nv_bfloat16 h = __float2bfloat16(acc);
        g_Wh[off] = h;
        g_Wl[off] = __float2bfloat16(acc - __bfloat162float(h));
    }
}

// ====== K5: bf16 GEMM, block 128x256, warp 64x64, ldmatrix + swizzle ========
// out = [Xh+Xl] @ [Wh+Wl]^T + bias  (3 terms: XhWh + XhWl + XlWh)
#define NSTG    4
#define KSTG    32
#define ATILE_B 8192                   // 128 rows * 64B
#define BTILE_B 16384                  // 256 rows * 64B
#define STAGE_B (2 * ATILE_B + 2 * BTILE_B)   // 49152

#define CP_ASYNC16(dst, src) \
    asm volatile("cp.async.cg.shared.global [%0], [%1], 16;" :: "r"(dst), "l"(src))
#define CP_COMMIT() asm volatile("cp.async.commit_group;" ::: "memory")
#define CP_WAIT2()  asm volatile("cp.async.wait_group 2;" ::: "memory")

__device__ __forceinline__ uint32_t smem_u32(const void* p) {
    uint32_t a;
    asm("{ .reg .u64 t; cvta.to.shared.u64 t, %1; cvt.u32.u64 %0, t; }" : "=r"(a) : "l"(p));
    return a;
}

__device__ __forceinline__ void ldsm4(uint32_t* r, uint32_t addr) {
    asm volatile("ldmatrix.sync.aligned.m8n8.x4.shared.b16 {%0,%1,%2,%3}, [%4];"
        : "=r"(r[0]), "=r"(r[1]), "=r"(r[2]), "=r"(r[3]) : "r"(addr));
}

__device__ __forceinline__ void mma16816(float* c, const uint32_t* a,
                                         uint32_t b0, uint32_t b1) {
    asm volatile(
        "mma.sync.aligned.m16n8k16.row.col.f32.bf16.bf16.f32 "
        "{%0,%1,%2,%3}, {%4,%5,%6,%7}, {%8,%9}, {%0,%1,%2,%3};\n"
        : "+f"(c[0]), "+f"(c[1]), "+f"(c[2]), "+f"(c[3])
        : "r"(a[0]), "r"(a[1]), "r"(a[2]), "r"(a[3]), "r"(b0), "r"(b1));
}

__global__ void __launch_bounds__(256, 1)
k_gemm(const float* __restrict__ bias, float* __restrict__ out)
{
    extern __shared__ __align__(128) char dsm[];
    uint32_t sbase = smem_u32(dsm);

    int tid  = threadIdx.x;
    int warp = tid >> 5, lane = tid & 31;
    int wm = warp & 1, wn = warp >> 1;     // 2(m) x 4(n), warp tile 64x64
    int g  = lane >> 2, tg = lane & 3;

    int bx = blockIdx.x;
    int m0 = (bx >> 4) * 128;
    int n0 = (bx & 15) * 256;

    // ---- ldmatrix base addresses (within a tile; 64B rows, XOR swizzle) ----
    int lrow = lane & 15, lhalf = lane >> 4;
    uint32_t baseA[4], baseB[4];
#pragma unroll
    for (int mt = 0; mt < 4; mt++) {
        int r = wm * 64 + mt * 16 + lrow;
        baseA[mt] = (uint32_t)(r * 64 + ((lhalf ^ ((r >> 1) & 3)) << 4));
    }
#pragma unroll
    for (int p = 0; p < 4; p++) {
        int r = wn * 64 + p * 16 + lrow;
        baseB[p] = (uint32_t)(r * 64 + ((lhalf ^ ((r >> 1) & 3)) << 4));
    }

    // ---- cp.async assignments: 12 x 16B chunks per thread per stage ----
    // stage layout: Xh @0 (512 chunks), Xl @8K (512), Wh @16K (1024), Wl @32K (1024)
    const char* gsrc[12];
    uint32_t sdst[12];
#pragma unroll
    for (int j = 0; j < 12; j++) {
        int idx = tid + 256 * j;           // 0..3071
        const char* gbase;
        uint32_t toff;
        int row, grow;
        if (idx < 512)       { gbase = (const char*)g_Xh; toff = 0;
                               row = idx >> 2;           grow = m0 + row; }
        else if (idx < 1024) { gbase = (const char*)g_Xl; toff = ATILE_B;
                               row = (idx - 512) >> 2;   grow = m0 + row; }
        else if (idx < 2048) { gbase = (const char*)g_Wh; toff = 2 * ATILE_B;
                               row = (idx - 1024) >> 2;  grow = n0 + row; }
        else                 { gbase = (const char*)g_Wl; toff = 2 * ATILE_B + BTILE_B;
                               row = (idx - 2048) >> 2;  grow = n0 + row; }
        int c4 = idx & 3;
        gsrc[j] = gbase + ((size_t)grow * IN_F + c4 * 8) * 2;
        sdst[j] = sbase + toff + row * 64
                + (uint32_t)(((c4 ^ ((row >> 1) & 3)) << 4));
    }

    float acc[4][8][4];
#pragma unroll
    for (int a = 0; a < 4; a++)
#pragma unroll
        for (int b = 0; b < 8; b++)
#pragma unroll
            for (int c = 0; c < 4; c++) acc[a][b][c] = 0.f;

    const int NKB = IN_F / KSTG;   // 128

    // prologue: stages 0..2
#pragma unroll
    for (int s = 0; s < NSTG - 1; s++) {
        uint32_t so = s * STAGE_B;
        long ko = (long)s * (KSTG * 2);
#pragma unroll
        for (int j = 0; j < 12; j++) CP_ASYNC16(sdst[j] + so, gsrc[j] + ko);
        CP_COMMIT();
    }

    for (int kb = 0; kb < NKB; kb++) {
        CP_WAIT2();
        __syncthreads();

        if (kb + NSTG - 1 < NKB) {
            int st = kb + NSTG - 1;
            uint32_t so = (uint32_t)((st & (NSTG - 1)) * STAGE_B);
            long ko = (long)st * (KSTG * 2);
#pragma unroll
            for (int j = 0; j < 12; j++) CP_ASYNC16(sdst[j] + so, gsrc[j] + ko);
        }
        CP_COMMIT();

        uint32_t stg = sbase + (uint32_t)((kb & (NSTG - 1)) * STAGE_B);
        uint32_t sXh = stg, sXl = stg + ATILE_B;
        uint32_t sWh = stg + 2 * ATILE_B, sWl = stg + 2 * ATILE_B + BTILE_B;

#pragma unroll
        for (int ks = 0; ks < 2; ks++) {
            uint32_t kx = ks ? 32u : 0u;
            uint32_t Ah[16], Bh[16], Tt[16];
#pragma unroll
            for (int mt = 0; mt < 4; mt++) ldsm4(Ah + 4 * mt, sXh + (baseA[mt] ^ kx));
#pragma unroll
            for (int p = 0; p < 4; p++)    ldsm4(Bh + 4 * p,  sWh + (baseB[p] ^ kx));
#pragma unroll
            for (int mt = 0; mt < 4; mt++)
#pragma unroll
                for (int nt = 0; nt < 8; nt++) {
                    int p = nt >> 1, o = nt & 1;
                    mma16816(acc[mt][nt], Ah + 4 * mt, Bh[p * 4 + o], Bh[p * 4 + 2 + o]);
                }
            // hi(A) * lo(B)
#pragma unroll
            for (int p = 0; p < 4; p++)    ldsm4(Tt + 4 * p,  sWl + (baseB[p] ^ kx));
#pragma unroll
            for (int mt = 0; mt < 4; mt++)
#pragma unroll
                for (int nt = 0; nt < 8; nt++) {
                    int p = nt >> 1, o = nt & 1;
                    mma16816(acc[mt][nt], Ah + 4 * mt, Tt[p * 4 + o], Tt[p * 4 + 2 + o]);
                }
            // lo(A) * hi(B)
#pragma unroll
            for (int mt = 0; mt < 4; mt++) ldsm4(Tt + 4 * mt, sXl + (baseA[mt] ^ kx));
#pragma unroll
            for (int mt = 0; mt < 4; mt++)
#pragma unroll
                for (int nt = 0; nt < 8; nt++) {
                    int p = nt >> 1, o = nt & 1;
                    mma16816(acc[mt][nt], Tt + 4 * mt, Bh[p * 4 + o], Bh[p * 4 + 2 + o]);
                }
        }
        __syncthreads();
    }

    // epilogue: + bias, store fp32
#pragma unroll
    for (int nt = 0; nt < 8; nt++) {
        int c = n0 + wn * 64 + nt * 8 + tg * 2;
        float b0 = __ldg(&bias[c]);
        float b1 = __ldg(&bias[c + 1]);
#pragma unroll
        for (int mt = 0; mt < 4; mt++) {
            int r0 = m0 + wm * 64 + mt * 16 + g;
            float2 v0, v1;
            v0.x = acc[mt][nt][0] + b0;
            v0.y = acc[mt][nt][1] + b1;
            v1.x = acc[mt][nt][2] + b0;
            v1.y = acc[mt][nt][3] + b1;
            *(float2*)&out[(size_t)r0 * OUT_F + c]       = v0;
            *(float2*)&out[(size_t)(r0 + 8) * OUT_F + c] = v1;
        }
    }
}

// ================= launch =================
extern "C" void kernel_launch(void* const* d_in, const int* in_sizes, int n_in,
                              void* d_out, int out_size) {
    const float* x    = (const float*)d_in[0];
    const float* W    = (const float*)d_in[1];
    const float* bias = (const float*)d_in[2];
    const float* lA   = (const float*)d_in[3];
    const float* lB   = (const float*)d_in[4];
    float* out = (float*)d_out;

    // launch order chosen so k_gemm is launch index 5 (ncu -s 5 -c 1)
    k_zero<<<1, 256>>>();
    k_sc<<<16, 256>>>(lA, lB);
    k_ns<<<1, 256>>>();
    k_aq<<<16, 256>>>(lA);
    k_prep<<<XSPLIT_BLOCKS + (IN_F / 256) * (OUT_F / 64), 256>>>(x, W, lB);

    static int smem_set = 0;
    int smem_sz = NSTG * STAGE_B;   // 196608
    if (!smem_set) {
        cudaFuncSetAttribute(k_gemm, cudaFuncAttributeMaxDynamicSharedMemorySize, smem_sz);
        smem_set = 1;
    }
    int nblocks = (TOKENS / 128) * (OUT_F / 256);   // 1024
    k_gemm<<<nblocks, 256, smem_sz>>>(bias, out);
}

// round 7
// speedup vs baseline: 1.5926x; 1.5926x over previous
#include <cuda_runtime.h>
#include <cuda_bf16.h>
#include <cuda_fp16.h>
#include <stdint.h>

#define TOKENS 8192
#define IN_F   4096
#define OUT_F  4096
#define RNK    16

// ================= device scratch (no allocs allowed) =================
__device__ float g_Sp[16][256];                     // per-block partials of S
__device__ float g_Cp[16][256];                     // per-block partials of C
__device__ float g_Qs[256];                         // alpha * Q5
__device__ __align__(1024) __half g_Xs[(size_t)TOKENS * IN_F];   // fp16(x)
__device__ __align__(1024) __half g_Wh[(size_t)OUT_F * IN_F];    // fp16 hi of W'
__device__ __align__(1024) __half g_Wl[(size_t)OUT_F * IN_F];    // fp16 lo of W'

// ========== K0: S,C gram partials (no init needed — direct store) ==========
__global__ void k_sc(const float* __restrict__ lA, const float* __restrict__ lB) {
    int t = threadIdx.x, i = t >> 4, j = t & 15;
    int b = blockIdx.x;
    int k0 = b * 256;
    const float4* Ai = (const float4*)(lA + (size_t)i * IN_F);
    const float4* Aj = (const float4*)(lA + (size_t)j * IN_F);
    float s = 0.f;
#pragma unroll 8
    for (int k4 = k0 / 4; k4 < k0 / 4 + 64; k4++) {
        float4 a = Ai[k4], bb = Aj[k4];
        s += a.x * bb.x + a.y * bb.y + a.z * bb.z + a.w * bb.w;
    }
    float c = 0.f;
#pragma unroll 4
    for (int k = k0; k < k0 + 256; k++)
        c += lB[(size_t)k * RNK + i] * lB[(size_t)k * RNK + j];
    g_Sp[b][t] = s;
    g_Cp[b][t] = c;
}

// ========== K1: reduce partials + Newton-Schulz in rank-16 space ==========
__global__ void k_ns() {
    __shared__ float S[256], C[256], Q[256], Rm[256], T1[256], T2[256], P[256], W2[256];
    int t = threadIdx.x, i = t >> 4, j = t & 15;
    float sacc = 0.f, cacc = 0.f;
#pragma unroll
    for (int b = 0; b < 16; b++) { sacc += g_Sp[b][t]; cacc += g_Cp[b][t]; }
    S[t] = sacc; C[t] = cacc;
    __syncthreads();
    W2[t] = S[i * 16 + j] * C[j * 16 + i];
    __syncthreads();
    for (int s = 128; s; s >>= 1) { if (t < s) W2[t] += W2[t + s]; __syncthreads(); }
    float alpha = sqrtf(W2[0]);
    float nrm = alpha + 1e-7f;
    Q[t] = (i == j) ? (1.f / nrm) : 0.f;
    Rm[t] = C[t] / (nrm * nrm);
    __syncthreads();
    const float ca = 3.4445f, cb = -4.775f, cc = 2.0315f;
    for (int step = 0; step < 5; step++) {
        float acc = 0.f;
#pragma unroll
        for (int k = 0; k < 16; k++) acc += S[i * 16 + k] * Rm[k * 16 + j];
        T1[t] = acc; __syncthreads();
        acc = 0.f;
#pragma unroll
        for (int k = 0; k < 16; k++) acc += T1[i * 16 + k] * T1[k * 16 + j];
        T2[t] = acc; __syncthreads();
        P[t] = cc * T2[t] + cb * T1[t] + ((i == j) ? ca : 0.f);
        __syncthreads();
        acc = 0.f;
#pragma unroll
        for (int k = 0; k < 16; k++) acc += Q[i * 16 + k] * P[k * 16 + j];
        W2[t] = acc; __syncthreads(); Q[t] = W2[t];
        acc = 0.f;
#pragma unroll
        for (int k = 0; k < 16; k++) acc += Rm[i * 16 + k] * P[k * 16 + j];
        W2[t] = acc; __syncthreads();
        acc = 0.f;
#pragma unroll
        for (int k = 0; k < 16; k++) acc += P[k * 16 + i] * W2[k * 16 + j];
        T1[t] = acc; __syncthreads(); Rm[t] = T1[t]; __syncthreads();
    }
    g_Qs[t] = alpha * Q[t];
}

// == K2 (merged prep): x -> fp16; W' = W + lB@((aQ5)@lA) -> fp16 hi/lo split ==
#define XSPLIT_BLOCKS 32768    // (TOKENS * IN_F / 4) / 256
__global__ void k_prep(const float* __restrict__ x, const float* __restrict__ W,
                       const float* __restrict__ lA, const float* __restrict__ lB) {
    if (blockIdx.x < XSPLIT_BLOCKS) {
        size_t i = (size_t)blockIdx.x * 256 + threadIdx.x;   // float4 index
        float4 v = ((const float4*)x)[i];
        __half2 a; a.x = __float2half_rn(v.x); a.y = __float2half_rn(v.y);
        __half2 b; b.x = __float2half_rn(v.z); b.y = __float2half_rn(v.w);
        ((__half2*)g_Xs)[i * 2]     = a;
        ((__half2*)g_Xs)[i * 2 + 1] = b;
        return;
    }
    // W-fold block: compute Aq = (aQ5)@lA inline for this column chunk
    __shared__ float sA[16 * 256];
    __shared__ float sQ[256];
    __shared__ float sB[64 * 16];
    int b = blockIdx.x - XSPLIT_BLOCKS;
    int tid = threadIdx.x;
    int c0 = (b & 15) * 256, i0 = (b >> 4) * 64;
#pragma unroll
    for (int q = 0; q < 16; q++) {
        int i = tid + 256 * q;
        sA[i] = lA[(size_t)(i >> 8) * IN_F + c0 + (i & 255)];
    }
    sQ[tid] = g_Qs[tid];
#pragma unroll
    for (int q = 0; q < 4; q++) {
        int i = tid + 256 * q;
        sB[i] = lB[(size_t)(i0 + (i >> 4)) * RNK + (i & 15)];
    }
    __syncthreads();
    int col = c0 + tid;
    float av[16];
#pragma unroll
    for (int s = 0; s < 16; s++) av[s] = sA[s * 256 + tid];
    float aq[16];
#pragma unroll
    for (int r = 0; r < 16; r++) {
        float acc = 0.f;
#pragma unroll
        for (int s = 0; s < 16; s++) acc += sQ[r * 16 + s] * av[s];
        aq[r] = acc;
    }
    for (int ir = 0; ir < 64; ir++) {
        size_t off = (size_t)(i0 + ir) * IN_F + col;
        float acc = W[off];
#pragma unroll
        for (int r = 0; r < 16; r++) acc += sB[ir * 16 + r] * aq[r];
        __half h = __float2half_rn(acc);
        g_Wh[off] = h;
        g_Wl[off] = __float2half_rn(acc - __half2float(h));
    }
}

// ======= K3: fp16 GEMM, block 128x128, warp 64x32, 2-term W-split ==========
// out = Xs @ (Wh + Wl)^T + bias   (Xs=fp16(x); Wh+Wl = 22-bit fp16 split of W')
#define NSTG    4
#define KSTG    32
#define TILE_B  8192                   // 128 rows * 64B
#define STAGE_B (3 * TILE_B)           // 24576 (Xs, Wh, Wl)

#define CP_ASYNC16(dst, src) \
    asm volatile("cp.async.cg.shared.global [%0], [%1], 16;" :: "r"(dst), "l"(src))
#define CP_COMMIT() asm volatile("cp.async.commit_group;" ::: "memory")
#define CP_WAIT2()  asm volatile("cp.async.wait_group 2;" ::: "memory")

__device__ __forceinline__ uint32_t smem_u32(const void* p) {
    uint32_t a;
    asm("{ .reg .u64 t; cvta.to.shared.u64 t, %1; cvt.u32.u64 %0, t; }" : "=r"(a) : "l"(p));
    return a;
}

__device__ __forceinline__ void ldsm4(uint32_t* r, uint32_t addr) {
    asm volatile("ldmatrix.sync.aligned.m8n8.x4.shared.b16 {%0,%1,%2,%3}, [%4];"
        : "=r"(r[0]), "=r"(r[1]), "=r"(r[2]), "=r"(r[3]) : "r"(addr));
}

__device__ __forceinline__ void mma16816(float* c, const uint32_t* a,
                                         uint32_t b0, uint32_t b1) {
    asm volatile(
        "mma.sync.aligned.m16n8k16.row.col.f32.f16.f16.f32 "
        "{%0,%1,%2,%3}, {%4,%5,%6,%7}, {%8,%9}, {%0,%1,%2,%3};\n"
        : "+f"(c[0]), "+f"(c[1]), "+f"(c[2]), "+f"(c[3])
        : "r"(a[0]), "r"(a[1]), "r"(a[2]), "r"(a[3]), "r"(b0), "r"(b1));
}

__global__ void __launch_bounds__(256, 2)
k_gemm(const float* __restrict__ bias, float* __restrict__ out)
{
    extern __shared__ __align__(128) char dsm[];
    uint32_t sbase = smem_u32(dsm);

    int tid  = threadIdx.x;
    int warp = tid >> 5, lane = tid & 31;
    int wm = warp & 1, wn = warp >> 1;     // 2(m) x 4(n) warps, warp tile 64x32
    int g  = lane >> 2, tg = lane & 3;

    int bx = blockIdx.x;
    int m0 = (bx >> 5) * 128;
    int n0 = (bx & 31) * 128;

    // ---- ldmatrix base addresses (64B rows, XOR swizzle: validated R5) ----
    int lrow = lane & 15, lhalf = lane >> 4;
    uint32_t baseA[4], baseB[2];
#pragma unroll
    for (int mt = 0; mt < 4; mt++) {
        int r = wm * 64 + mt * 16 + lrow;
        baseA[mt] = (uint32_t)(r * 64 + ((lhalf ^ ((r >> 1) & 3)) << 4));
    }
#pragma unroll
    for (int p = 0; p < 2; p++) {
        int r = wn * 32 + p * 16 + lrow;
        baseB[p] = (uint32_t)(r * 64 + ((lhalf ^ ((r >> 1) & 3)) << 4));
    }

    // ---- cp.async assignments: 6 x 16B chunks per thread per stage ----
    const char* gsrc[6];
    uint32_t sdst[6];
    {
        const char* basep[3] = { (const char*)g_Xs, (const char*)g_Wh,
                                 (const char*)g_Wl };
#pragma unroll
        for (int j = 0; j < 6; j++) {
            int idx  = tid + 256 * j;       // 0..1535
            int tile = idx >> 9;            // 0..2
            int c    = idx & 511;
            int row  = c >> 2;              // 0..127
            int c4   = c & 3;               // 16B chunk in 64B row
            int grow = (tile == 0 ? m0 : n0) + row;
            gsrc[j] = basep[tile] + ((size_t)grow * IN_F + c4 * 8) * 2;
            sdst[j] = sbase + tile * TILE_B + row * 64
                    + (uint32_t)(((c4 ^ ((row >> 1) & 3)) << 4));
        }
    }

    float acc[4][4][4];
#pragma unroll
    for (int a = 0; a < 4; a++)
#pragma unroll
        for (int b = 0; b < 4; b++)
#pragma unroll
            for (int c = 0; c < 4; c++) acc[a][b][c] = 0.f;

    const int NKB = IN_F / KSTG;   // 128

    // prologue: stages 0..2
#pragma unroll
    for (int s = 0; s < NSTG - 1; s++) {
        uint32_t so = s * STAGE_B;
        long ko = (long)s * (KSTG * 2);
#pragma unroll
        for (int j = 0; j < 6; j++) CP_ASYNC16(sdst[j] + so, gsrc[j] + ko);
        CP_COMMIT();
    }

    for (int kb = 0; kb < NKB; kb++) {
        CP_WAIT2();
        __syncthreads();

        if (kb + NSTG - 1 < NKB) {
            int st = kb + NSTG - 1;
            uint32_t so = (uint32_t)((st & (NSTG - 1)) * STAGE_B);
            long ko = (long)st * (KSTG * 2);
#pragma unroll
            for (int j = 0; j < 6; j++) CP_ASYNC16(sdst[j] + so, gsrc[j] + ko);
        }
        CP_COMMIT();

        uint32_t stg = sbase + (uint32_t)((kb & (NSTG - 1)) * STAGE_B);
        uint32_t sXs = stg;
        uint32_t sWh = stg + TILE_B;
        uint32_t sWl = stg + 2 * TILE_B;

#pragma unroll
        for (int ks = 0; ks < 2; ks++) {
            uint32_t kx = ks ? 32u : 0u;   // flips chunk-sel bit (k-half pair)
            uint32_t Ah[16], Bh[8], Bl[8];
#pragma unroll
            for (int mt = 0; mt < 4; mt++) ldsm4(Ah + 4 * mt, sXs + (baseA[mt] ^ kx));
#pragma unroll
            for (int p = 0; p < 2; p++)    ldsm4(Bh + 4 * p,  sWh + (baseB[p] ^ kx));
#pragma unroll
            for (int p = 0; p < 2; p++)    ldsm4(Bl + 4 * p,  sWl + (baseB[p] ^ kx));
#pragma unroll
            for (int mt = 0; mt < 4; mt++)
#pragma unroll
                for (int nt = 0; nt < 4; nt++) {
                    int p = nt >> 1, o = nt & 1;
                    mma16816(acc[mt][nt], Ah + 4 * mt, Bh[p * 4 + o], Bh[p * 4 + 2 + o]);
                }
#pragma unroll
            for (int mt = 0; mt < 4; mt++)
#pragma unroll
                for (int nt = 0; nt < 4; nt++) {
                    int p = nt >> 1, o = nt & 1;
                    mma16816(acc[mt][nt], Ah + 4 * mt, Bl[p * 4 + o], Bl[p * 4 + 2 + o]);
                }
        }
        __syncthreads();
    }

    // epilogue: + bias, store fp32
#pragma unroll
    for (int nt = 0; nt < 4; nt++) {
        int c = n0 + wn * 32 + nt * 8 + tg * 2;
        float b0 = __ldg(&bias[c]);
        float b1 = __ldg(&bias[c + 1]);
#pragma unroll
        for (int mt = 0; mt < 4; mt++) {
            int r0 = m0 + wm * 64 + mt * 16 + g;
            float2 v0, v1;
            v0.x = acc[mt][nt][0] + b0;
            v0.y = acc[mt][nt][1] + b1;
            v1.x = acc[mt][nt][2] + b0;
            v1.y = acc[mt][nt][3] + b1;
            *(float2*)&out[(size_t)r0 * OUT_F + c]       = v0;
            *(float2*)&out[(size_t)(r0 + 8) * OUT_F + c] = v1;
        }
    }
}

// ================= launch =================
extern "C" void kernel_launch(void* const* d_in, const int* in_sizes, int n_in,
                              void* d_out, int out_size) {
    const float* x    = (const float*)d_in[0];
    const float* W    = (const float*)d_in[1];
    const float* bias = (const float*)d_in[2];
    const float* lA   = (const float*)d_in[3];
    const float* lB   = (const float*)d_in[4];
    float* out = (float*)d_out;

    // 4 launches total; k_gemm is launch index 3 -> global ncu index 5 (captured)
    k_sc<<<16, 256>>>(lA, lB);
    k_ns<<<1, 256>>>();
    k_prep<<<XSPLIT_BLOCKS + (IN_F / 256) * (OUT_F / 64), 256>>>(x, W, lA, lB);

    static int smem_set = 0;
    int smem_sz = NSTG * STAGE_B;   // 98304
    if (!smem_set) {
        cudaFuncSetAttribute(k_gemm, cudaFuncAttributeMaxDynamicSharedMemorySize, smem_sz);
        smem_set = 1;
    }
    int nblocks = (TOKENS / 128) * (OUT_F / 128);   // 2048
    k_gemm<<<nblocks, 256, smem_sz>>>(bias, out);
}

// round 9
// speedup vs baseline: 2.7821x; 1.7469x over previous
#include <cuda_runtime.h>
#include <cuda_fp16.h>
#include <stdint.h>

#define TOKENS 8192
#define IN_F   4096
#define OUT_F  4096
#define RNK    16

// ================= device scratch (no allocs allowed) =================
__device__ float g_Sp[16][256];                     // per-block partials of S
__device__ float g_Cp[16][256];                     // per-block partials of C
__device__ float g_Qs[256];                         // alpha * Q5
__device__ __align__(1024) __half g_Xs[(size_t)TOKENS * IN_F];   // fp16(x)
__device__ __align__(1024) __half g_Wh[(size_t)OUT_F * IN_F];    // fp16(W')

// ========== K0: S,C gram partials ==========
__global__ void k_sc(const float* __restrict__ lA, const float* __restrict__ lB) {
    int t = threadIdx.x, i = t >> 4, j = t & 15;
    int b = blockIdx.x;
    int k0 = b * 256;
    const float4* Ai = (const float4*)(lA + (size_t)i * IN_F);
    const float4* Aj = (const float4*)(lA + (size_t)j * IN_F);
    float s = 0.f;
#pragma unroll 8
    for (int k4 = k0 / 4; k4 < k0 / 4 + 64; k4++) {
        float4 a = Ai[k4], bb = Aj[k4];
        s += a.x * bb.x + a.y * bb.y + a.z * bb.z + a.w * bb.w;
    }
    float c = 0.f;
#pragma unroll 4
    for (int k = k0; k < k0 + 256; k++)
        c += lB[(size_t)k * RNK + i] * lB[(size_t)k * RNK + j];
    g_Sp[b][t] = s;
    g_Cp[b][t] = c;
}

// ========== K1: reduce partials + Newton-Schulz in rank-16 space ==========
__global__ void k_ns() {
    __shared__ float S[256], C[256], Q[256], Rm[256], T1[256], T2[256], P[256], W2[256];
    int t = threadIdx.x, i = t >> 4, j = t & 15;
    float sacc = 0.f, cacc = 0.f;
#pragma unroll
    for (int b = 0; b < 16; b++) { sacc += g_Sp[b][t]; cacc += g_Cp[b][t]; }
    S[t] = sacc; C[t] = cacc;
    __syncthreads();
    W2[t] = S[i * 16 + j] * C[j * 16 + i];
    __syncthreads();
    for (int s = 128; s; s >>= 1) { if (t < s) W2[t] += W2[t + s]; __syncthreads(); }
    float alpha = sqrtf(W2[0]);
    float nrm = alpha + 1e-7f;
    Q[t] = (i == j) ? (1.f / nrm) : 0.f;
    Rm[t] = C[t] / (nrm * nrm);
    __syncthreads();
    const float ca = 3.4445f, cb = -4.775f, cc = 2.0315f;
    for (int step = 0; step < 5; step++) {
        float acc = 0.f;
#pragma unroll
        for (int k = 0; k < 16; k++) acc += S[i * 16 + k] * Rm[k * 16 + j];
        T1[t] = acc; __syncthreads();
        acc = 0.f;
#pragma unroll
        for (int k = 0; k < 16; k++) acc += T1[i * 16 + k] * T1[k * 16 + j];
        T2[t] = acc; __syncthreads();
        P[t] = cc * T2[t] + cb * T1[t] + ((i == j) ? ca : 0.f);
        __syncthreads();
        acc = 0.f;
#pragma unroll
        for (int k = 0; k < 16; k++) acc += Q[i * 16 + k] * P[k * 16 + j];
        W2[t] = acc; __syncthreads(); Q[t] = W2[t];
        acc = 0.f;
#pragma unroll
        for (int k = 0; k < 16; k++) acc += Rm[i * 16 + k] * P[k * 16 + j];
        W2[t] = acc; __syncthreads();
        acc = 0.f;
#pragma unroll
        for (int k = 0; k < 16; k++) acc += P[k * 16 + i] * W2[k * 16 + j];
        T1[t] = acc; __syncthreads(); Rm[t] = T1[t]; __syncthreads();
    }
    g_Qs[t] = alpha * Q[t];
}

// ====== K2 (merged prep): x -> fp16;  W' = W + lB@((aQ5)@lA) -> fp16 ======
#define XSPLIT_BLOCKS 32768    // (TOKENS * IN_F / 4) / 256
__global__ void k_prep(const float* __restrict__ x, const float* __restrict__ W,
                       const float* __restrict__ lA, const float* __restrict__ lB) {
    if (blockIdx.x < XSPLIT_BLOCKS) {
        size_t i = (size_t)blockIdx.x * 256 + threadIdx.x;   // float4 index
        float4 v = ((const float4*)x)[i];
        __half2 a; a.x = __float2half_rn(v.x); a.y = __float2half_rn(v.y);
        __half2 b; b.x = __float2half_rn(v.z); b.y = __float2half_rn(v.w);
        ((__half2*)g_Xs)[i * 2]     = a;
        ((__half2*)g_Xs)[i * 2 + 1] = b;
        return;
    }
    __shared__ float sA[16 * 256];
    __shared__ float sQ[256];
    __shared__ float sB[64 * 16];
    int b = blockIdx.x - XSPLIT_BLOCKS;
    int tid = threadIdx.x;
    int c0 = (b & 15) * 256, i0 = (b >> 4) * 64;
#pragma unroll
    for (int q = 0; q < 16; q++) {
        int i = tid + 256 * q;
        sA[i] = lA[(size_t)(i >> 8) * IN_F + c0 + (i & 255)];
    }
    sQ[tid] = g_Qs[tid];
#pragma unroll
    for (int q = 0; q < 4; q++) {
        int i = tid + 256 * q;
        sB[i] = lB[(size_t)(i0 + (i >> 4)) * RNK + (i & 15)];
    }
    __syncthreads();
    int col = c0 + tid;
    float av[16];
#pragma unroll
    for (int s = 0; s < 16; s++) av[s] = sA[s * 256 + tid];
    float aq[16];
#pragma unroll
    for (int r = 0; r < 16; r++) {
        float acc = 0.f;
#pragma unroll
        for (int s = 0; s < 16; s++) acc += sQ[r * 16 + s] * av[s];
        aq[r] = acc;
    }
    for (int ir = 0; ir < 64; ir++) {
        size_t off = (size_t)(i0 + ir) * IN_F + col;
        float acc = W[off];
#pragma unroll
        for (int r = 0; r < 16; r++) acc += sB[ir * 16 + r] * aq[r];
        g_Wh[off] = __float2half_rn(acc);
    }
}

// ===== K3: single-term fp16 GEMM, block 128x128, warp 64x32, NSTG=6 ========
// out = Xs @ Wh^T + bias
#define NSTG    6
#define KSTG    32
#define TILE_B  8192                   // 128 rows * 64B
#define STAGE_B (2 * TILE_B)           // 16384 (Xs, Wh)

#define CP_ASYNC16(dst, src) \
    asm volatile("cp.async.cg.shared.global [%0], [%1], 16;" :: "r"(dst), "l"(src))
#define CP_COMMIT() asm volatile("cp.async.commit_group;" ::: "memory")
#define CP_WAIT4()  asm volatile("cp.async.wait_group 4;" ::: "memory")

__device__ __forceinline__ uint32_t smem_u32(const void* p) {
    uint32_t a;
    asm("{ .reg .u64 t; cvta.to.shared.u64 t, %1; cvt.u32.u64 %0, t; }" : "=r"(a) : "l"(p));
    return a;
}

__device__ __forceinline__ void ldsm4(uint32_t* r, uint32_t addr) {
    asm volatile("ldmatrix.sync.aligned.m8n8.x4.shared.b16 {%0,%1,%2,%3}, [%4];"
        : "=r"(r[0]), "=r"(r[1]), "=r"(r[2]), "=r"(r[3]) : "r"(addr));
}

__device__ __forceinline__ void mma16816(float* c, const uint32_t* a,
                                         uint32_t b0, uint32_t b1) {
    asm volatile(
        "mma.sync.aligned.m16n8k16.row.col.f32.f16.f16.f32 "
        "{%0,%1,%2,%3}, {%4,%5,%6,%7}, {%8,%9}, {%0,%1,%2,%3};\n"
        : "+f"(c[0]), "+f"(c[1]), "+f"(c[2]), "+f"(c[3])
        : "r"(a[0]), "r"(a[1]), "r"(a[2]), "r"(a[3]), "r"(b0), "r"(b1));
}

__global__ void __launch_bounds__(256, 2)
k_gemm(const float* __restrict__ bias, float* __restrict__ out)
{
    extern __shared__ __align__(128) char dsm[];
    uint32_t sbase = smem_u32(dsm);

    int tid  = threadIdx.x;
    int warp = tid >> 5, lane = tid & 31;
    int wm = warp & 1, wn = warp >> 1;     // 2(m) x 4(n) warps, warp tile 64x32
    int g  = lane >> 2, tg = lane & 3;

    int bx = blockIdx.x;
    int m0 = (bx >> 5) * 128;
    int n0 = (bx & 31) * 128;

    // ---- ldmatrix base addresses (64B rows, XOR swizzle: validated) ----
    int lrow = lane & 15, lhalf = lane >> 4;
    uint32_t baseA[4], baseB[2];
#pragma unroll
    for (int mt = 0; mt < 4; mt++) {
        int r = wm * 64 + mt * 16 + lrow;
        baseA[mt] = (uint32_t)(r * 64 + ((lhalf ^ ((r >> 1) & 3)) << 4));
    }
#pragma unroll
    for (int p = 0; p < 2; p++) {
        int r = wn * 32 + p * 16 + lrow;
        baseB[p] = (uint32_t)(r * 64 + ((lhalf ^ ((r >> 1) & 3)) << 4));
    }

    // ---- cp.async assignments: 4 x 16B chunks per thread per stage ----
    const char* gsrc[4];
    uint32_t sdst[4];
    {
        const char* basep[2] = { (const char*)g_Xs, (const char*)g_Wh };
#pragma unroll
        for (int j = 0; j < 4; j++) {
            int idx  = tid + 256 * j;       // 0..1023
            int tile = idx >> 9;            // 0..1
            int c    = idx & 511;
            int row  = c >> 2;              // 0..127
            int c4   = c & 3;               // 16B chunk in 64B row
            int grow = (tile == 0 ? m0 : n0) + row;
            gsrc[j] = basep[tile] + ((size_t)grow * IN_F + c4 * 8) * 2;
            sdst[j] = sbase + tile * TILE_B + row * 64
                    + (uint32_t)(((c4 ^ ((row >> 1) & 3)) << 4));
        }
    }

    float acc[4][4][4];
#pragma unroll
    for (int a = 0; a < 4; a++)
#pragma unroll
        for (int b = 0; b < 4; b++)
#pragma unroll
            for (int c = 0; c < 4; c++) acc[a][b][c] = 0.f;

    const int NKB = IN_F / KSTG;   // 128

    // prologue: stages 0..4
#pragma unroll
    for (int s = 0; s < NSTG - 1; s++) {
        uint32_t so = s * STAGE_B;
        long ko = (long)s * (KSTG * 2);
#pragma unroll
        for (int j = 0; j < 4; j++) CP_ASYNC16(sdst[j] + so, gsrc[j] + ko);
        CP_COMMIT();
    }

    int stage = 0;           // kb % NSTG
    int wstage = NSTG - 1;   // (kb + NSTG-1) % NSTG
    for (int kb = 0; kb < NKB; kb++) {
        CP_WAIT4();
        __syncthreads();     // all warps done reading stage (kb-1)%NSTG

        if (kb + NSTG - 1 < NKB) {
            int st = kb + NSTG - 1;
            uint32_t so = (uint32_t)(wstage * STAGE_B);
            long ko = (long)st * (KSTG * 2);
#pragma unroll
            for (int j = 0; j < 4; j++) CP_ASYNC16(sdst[j] + so, gsrc[j] + ko);
        }
        CP_COMMIT();

        uint32_t stg = sbase + (uint32_t)(stage * STAGE_B);
        uint32_t sXs = stg;
        uint32_t sWh = stg + TILE_B;

#pragma unroll
        for (int ks = 0; ks < 2; ks++) {
            uint32_t kx = ks ? 32u : 0u;   // flips chunk-sel bit (k-half pair)
            uint32_t Ah[16], Bh[8];
#pragma unroll
            for (int mt = 0; mt < 4; mt++) ldsm4(Ah + 4 * mt, sXs + (baseA[mt] ^ kx));
#pragma unroll
            for (int p = 0; p < 2; p++)    ldsm4(Bh + 4 * p,  sWh + (baseB[p] ^ kx));
#pragma unroll
            for (int mt = 0; mt < 4; mt++)
#pragma unroll
                for (int nt = 0; nt < 4; nt++) {
                    int p = nt >> 1, o = nt & 1;
                    mma16816(acc[mt][nt], Ah + 4 * mt, Bh[p * 4 + o], Bh[p * 4 + 2 + o]);
                }
        }
        // no trailing __syncthreads: next iteration's leading barrier protects reuse
        if (++stage == NSTG) stage = 0;
        if (++wstage == NSTG) wstage = 0;
    }

    // epilogue: + bias, store fp32
#pragma unroll
    for (int nt = 0; nt < 4; nt++) {
        int c = n0 + wn * 32 + nt * 8 + tg * 2;
        float b0 = __ldg(&bias[c]);
        float b1 = __ldg(&bias[c + 1]);
#pragma unroll
        for (int mt = 0; mt < 4; mt++) {
            int r0 = m0 + wm * 64 + mt * 16 + g;
            float2 v0, v1;
            v0.x = acc[mt][nt][0] + b0;
            v0.y = acc[mt][nt][1] + b1;
            v1.x = acc[mt][nt][2] + b0;
            v1.y = acc[mt][nt][3] + b1;
            *(float2*)&out[(size_t)r0 * OUT_F + c]       = v0;
            *(float2*)&out[(size_t)(r0 + 8) * OUT_F + c] = v1;
        }
    }
}

// ================= launch =================
extern "C" void kernel_launch(void* const* d_in, const int* in_sizes, int n_in,
                              void* d_out, int out_size) {
    const float* x    = (const float*)d_in[0];
    const float* W    = (const float*)d_in[1];
    const float* bias = (const float*)d_in[2];
    const float* lA   = (const float*)d_in[3];
    const float* lB   = (const float*)d_in[4];
    float* out = (float*)d_out;

    // k_gemm stays at launch index 3 (the ncu-captured slot)
    k_sc<<<16, 256>>>(lA, lB);
    k_ns<<<1, 256>>>();
    k_prep<<<XSPLIT_BLOCKS + (IN_F / 256) * (OUT_F / 64), 256>>>(x, W, lA, lB);

    static int smem_set = 0;
    int smem_sz = NSTG * STAGE_B;   // 98304
    if (!smem_set) {
        cudaFuncSetAttribute(k_gemm, cudaFuncAttributeMaxDynamicSharedMemorySize, smem_sz);
        smem_set = 1;
    }
    int nblocks = (TOKENS / 128) * (OUT_F / 128);   // 2048
    k_gemm<<<nblocks, 256, smem_sz>>>(bias, out);
}

// round 10
// speedup vs baseline: 2.8781x; 1.0345x over previous
#include <cuda_runtime.h>
#include <cuda_fp16.h>
#include <stdint.h>

#define TOKENS 8192
#define IN_F   4096
#define OUT_F  4096
#define RNK    16

// ================= device scratch (no allocs allowed) =================
__device__ float g_Sp[16][256];                     // per-block partials of S
__device__ float g_Cp[16][256];                     // per-block partials of C
__device__ float g_Qs[256];                         // alpha * Q5
__device__ __align__(1024) __half g_Xs[(size_t)TOKENS * IN_F];   // fp16(x)
__device__ __align__(1024) __half g_Wh[(size_t)OUT_F * IN_F];    // fp16(W')

// ========== K0: S,C gram partials ==========
__global__ void k_sc(const float* __restrict__ lA, const float* __restrict__ lB) {
    int t = threadIdx.x, i = t >> 4, j = t & 15;
    int b = blockIdx.x;
    int k0 = b * 256;
    const float4* Ai = (const float4*)(lA + (size_t)i * IN_F);
    const float4* Aj = (const float4*)(lA + (size_t)j * IN_F);
    float s = 0.f;
#pragma unroll 8
    for (int k4 = k0 / 4; k4 < k0 / 4 + 64; k4++) {
        float4 a = Ai[k4], bb = Aj[k4];
        s += a.x * bb.x + a.y * bb.y + a.z * bb.z + a.w * bb.w;
    }
    float c = 0.f;
#pragma unroll 4
    for (int k = k0; k < k0 + 256; k++)
        c += lB[(size_t)k * RNK + i] * lB[(size_t)k * RNK + j];
    g_Sp[b][t] = s;
    g_Cp[b][t] = c;
}

// ========== K1: reduce partials + Newton-Schulz in rank-16 space ==========
__global__ void k_ns() {
    __shared__ float S[256], C[256], Q[256], Rm[256], T1[256], T2[256], P[256], W2[256];
    int t = threadIdx.x, i = t >> 4, j = t & 15;
    float sacc = 0.f, cacc = 0.f;
#pragma unroll
    for (int b = 0; b < 16; b++) { sacc += g_Sp[b][t]; cacc += g_Cp[b][t]; }
    S[t] = sacc; C[t] = cacc;
    __syncthreads();
    W2[t] = S[i * 16 + j] * C[j * 16 + i];
    __syncthreads();
    for (int s = 128; s; s >>= 1) { if (t < s) W2[t] += W2[t + s]; __syncthreads(); }
    float alpha = sqrtf(W2[0]);
    float nrm = alpha + 1e-7f;
    Q[t] = (i == j) ? (1.f / nrm) : 0.f;
    Rm[t] = C[t] / (nrm * nrm);
    __syncthreads();
    const float ca = 3.4445f, cb = -4.775f, cc = 2.0315f;
    for (int step = 0; step < 5; step++) {
        float acc = 0.f;
#pragma unroll
        for (int k = 0; k < 16; k++) acc += S[i * 16 + k] * Rm[k * 16 + j];
        T1[t] = acc; __syncthreads();
        acc = 0.f;
#pragma unroll
        for (int k = 0; k < 16; k++) acc += T1[i * 16 + k] * T1[k * 16 + j];
        T2[t] = acc; __syncthreads();
        P[t] = cc * T2[t] + cb * T1[t] + ((i == j) ? ca : 0.f);
        __syncthreads();
        acc = 0.f;
#pragma unroll
        for (int k = 0; k < 16; k++) acc += Q[i * 16 + k] * P[k * 16 + j];
        W2[t] = acc; __syncthreads(); Q[t] = W2[t];
        acc = 0.f;
#pragma unroll
        for (int k = 0; k < 16; k++) acc += Rm[i * 16 + k] * P[k * 16 + j];
        W2[t] = acc; __syncthreads();
        acc = 0.f;
#pragma unroll
        for (int k = 0; k < 16; k++) acc += P[k * 16 + i] * W2[k * 16 + j];
        T1[t] = acc; __syncthreads(); Rm[t] = T1[t]; __syncthreads();
    }
    g_Qs[t] = alpha * Q[t];
}

// ====== K2 (merged prep): x -> fp16;  W' = W + lB@((aQ5)@lA) -> fp16 ======
#define XSPLIT_BLOCKS 32768    // (TOKENS * IN_F / 4) / 256
__global__ void k_prep(const float* __restrict__ x, const float* __restrict__ W,
                       const float* __restrict__ lA, const float* __restrict__ lB) {
    if (blockIdx.x < XSPLIT_BLOCKS) {
        size_t i = (size_t)blockIdx.x * 256 + threadIdx.x;   // float4 index
        float4 v = ((const float4*)x)[i];
        __half2 a; a.x = __float2half_rn(v.x); a.y = __float2half_rn(v.y);
        __half2 b; b.x = __float2half_rn(v.z); b.y = __float2half_rn(v.w);
        ((__half2*)g_Xs)[i * 2]     = a;
        ((__half2*)g_Xs)[i * 2 + 1] = b;
        return;
    }
    __shared__ float sA[16 * 256];
    __shared__ float sQ[256];
    __shared__ float sB[64 * 16];
    int b = blockIdx.x - XSPLIT_BLOCKS;
    int tid = threadIdx.x;
    int c0 = (b & 15) * 256, i0 = (b >> 4) * 64;
#pragma unroll
    for (int q = 0; q < 16; q++) {
        int i = tid + 256 * q;
        sA[i] = lA[(size_t)(i >> 8) * IN_F + c0 + (i & 255)];
    }
    sQ[tid] = g_Qs[tid];
#pragma unroll
    for (int q = 0; q < 4; q++) {
        int i = tid + 256 * q;
        sB[i] = lB[(size_t)(i0 + (i >> 4)) * RNK + (i & 15)];
    }
    __syncthreads();
    int col = c0 + tid;
    float av[16];
#pragma unroll
    for (int s = 0; s < 16; s++) av[s] = sA[s * 256 + tid];
    float aq[16];
#pragma unroll
    for (int r = 0; r < 16; r++) {
        float acc = 0.f;
#pragma unroll
        for (int s = 0; s < 16; s++) acc += sQ[r * 16 + s] * av[s];
        aq[r] = acc;
    }
    for (int ir = 0; ir < 64; ir++) {
        size_t off = (size_t)(i0 + ir) * IN_F + col;
        float acc = W[off];
#pragma unroll
        for (int r = 0; r < 16; r++) acc += sB[ir * 16 + r] * aq[r];
        g_Wh[off] = __float2half_rn(acc);
    }
}

// ===== K3: fp16 GEMM, block 128x128, warp 64x32, KSTG=64, NSTG=3 ===========
// out = Xs @ Wh^T + bias
// Tile rows are 128B (64 halves); swizzle: chunk_eff = chunk ^ (row & 7).
#define NSTG    3
#define KSTG    64
#define TILE_B  16384                  // 128 rows * 128B
#define STAGE_B (2 * TILE_B)           // 32768 (Xs, Wh)

#define CP_ASYNC16(dst, src) \
    asm volatile("cp.async.cg.shared.global [%0], [%1], 16;" :: "r"(dst), "l"(src))
#define CP_COMMIT() asm volatile("cp.async.commit_group;" ::: "memory")
#define CP_WAIT1()  asm volatile("cp.async.wait_group 1;" ::: "memory")

__device__ __forceinline__ uint32_t smem_u32(const void* p) {
    uint32_t a;
    asm("{ .reg .u64 t; cvta.to.shared.u64 t, %1; cvt.u32.u64 %0, t; }" : "=r"(a) : "l"(p));
    return a;
}

__device__ __forceinline__ void ldsm4(uint32_t* r, uint32_t addr) {
    asm volatile("ldmatrix.sync.aligned.m8n8.x4.shared.b16 {%0,%1,%2,%3}, [%4];"
        : "=r"(r[0]), "=r"(r[1]), "=r"(r[2]), "=r"(r[3]) : "r"(addr));
}

__device__ __forceinline__ void mma16816(float* c, const uint32_t* a,
                                         uint32_t b0, uint32_t b1) {
    asm volatile(
        "mma.sync.aligned.m16n8k16.row.col.f32.f16.f16.f32 "
        "{%0,%1,%2,%3}, {%4,%5,%6,%7}, {%8,%9}, {%0,%1,%2,%3};\n"
        : "+f"(c[0]), "+f"(c[1]), "+f"(c[2]), "+f"(c[3])
        : "r"(a[0]), "r"(a[1]), "r"(a[2]), "r"(a[3]), "r"(b0), "r"(b1));
}

__global__ void __launch_bounds__(256, 2)
k_gemm(const float* __restrict__ bias, float* __restrict__ out)
{
    extern __shared__ __align__(128) char dsm[];
    uint32_t sbase = smem_u32(dsm);

    int tid  = threadIdx.x;
    int warp = tid >> 5, lane = tid & 31;
    int wm = warp & 1, wn = warp >> 1;     // 2(m) x 4(n) warps, warp tile 64x32
    int g  = lane >> 2, tg = lane & 3;

    int bx = blockIdx.x;
    int m0 = (bx >> 5) * 128;
    int n0 = (bx & 31) * 128;

    // ---- ldmatrix base addresses (128B rows, chunk ^= row&7 swizzle) ----
    // k16-slice ks: address = base ^ (ks << 5)   (ks*2 and lhalf use disjoint bits)
    int lrow = lane & 15, lhalf = lane >> 4;
    uint32_t baseA[4], baseB[2];
#pragma unroll
    for (int mt = 0; mt < 4; mt++) {
        int r = wm * 64 + mt * 16 + lrow;
        baseA[mt] = (uint32_t)(r * 128 + ((lhalf ^ (r & 7)) << 4));
    }
#pragma unroll
    for (int p = 0; p < 2; p++) {
        int r = wn * 32 + p * 16 + lrow;
        baseB[p] = (uint32_t)(r * 128 + ((lhalf ^ (r & 7)) << 4));
    }

    // ---- cp.async assignments: 8 x 16B chunks per thread per stage ----
    const char* gsrc[8];
    uint32_t sdst[8];
    {
        const char* basep[2] = { (const char*)g_Xs, (const char*)g_Wh };
#pragma unroll
        for (int j = 0; j < 8; j++) {
            int idx  = tid + 256 * j;        // 0..2047
            int tile = idx >> 10;            // 0..1 (1024 chunks per tile)
            int c    = idx & 1023;
            int row  = c >> 3;               // 0..127
            int c8   = c & 7;                // 16B chunk in 128B row
            int grow = (tile == 0 ? m0 : n0) + row;
            gsrc[j] = basep[tile] + ((size_t)grow * IN_F + c8 * 8) * 2;
            sdst[j] = sbase + tile * TILE_B + row * 128
                    + (uint32_t)(((c8 ^ (row & 7)) << 4));
        }
    }

    float acc[4][4][4];
#pragma unroll
    for (int a = 0; a < 4; a++)
#pragma unroll
        for (int b = 0; b < 4; b++)
#pragma unroll
            for (int c = 0; c < 4; c++) acc[a][b][c] = 0.f;

    const int NKB = IN_F / KSTG;   // 64

    // prologue: stages 0,1
#pragma unroll
    for (int s = 0; s < NSTG - 1; s++) {
        uint32_t so = s * STAGE_B;
#pragma unroll
        for (int j = 0; j < 8; j++) CP_ASYNC16(sdst[j] + so, gsrc[j]);
#pragma unroll
        for (int j = 0; j < 8; j++) gsrc[j] += KSTG * 2;
        CP_COMMIT();
    }

    int stage = 0;           // kb % NSTG
    int wstage = NSTG - 1;   // (kb + NSTG-1) % NSTG
    for (int kb = 0; kb < NKB; kb++) {
        CP_WAIT1();
        __syncthreads();     // all warps done reading stage (kb-1)%NSTG

        if (kb + NSTG - 1 < NKB) {
            uint32_t so = (uint32_t)(wstage * STAGE_B);
#pragma unroll
            for (int j = 0; j < 8; j++) CP_ASYNC16(sdst[j] + so, gsrc[j]);
#pragma unroll
            for (int j = 0; j < 8; j++) gsrc[j] += KSTG * 2;
        }
        CP_COMMIT();

        uint32_t stg = sbase + (uint32_t)(stage * STAGE_B);
        uint32_t sXs = stg;
        uint32_t sWh = stg + TILE_B;

#pragma unroll
        for (int ks = 0; ks < 4; ks++) {
            uint32_t kx = (uint32_t)(ks << 5);
            uint32_t Ah[16], Bh[8];
#pragma unroll
            for (int mt = 0; mt < 4; mt++) ldsm4(Ah + 4 * mt, sXs + (baseA[mt] ^ kx));
#pragma unroll
            for (int p = 0; p < 2; p++)    ldsm4(Bh + 4 * p,  sWh + (baseB[p] ^ kx));
#pragma unroll
            for (int mt = 0; mt < 4; mt++)
#pragma unroll
                for (int nt = 0; nt < 4; nt++) {
                    int p = nt >> 1, o = nt & 1;
                    mma16816(acc[mt][nt], Ah + 4 * mt, Bh[p * 4 + o], Bh[p * 4 + 2 + o]);
                }
        }
        // no trailing __syncthreads: next iteration's leading barrier protects reuse
        if (++stage == NSTG) stage = 0;
        if (++wstage == NSTG) wstage = 0;
    }

    // epilogue: + bias, store fp32
#pragma unroll
    for (int nt = 0; nt < 4; nt++) {
        int c = n0 + wn * 32 + nt * 8 + tg * 2;
        float b0 = __ldg(&bias[c]);
        float b1 = __ldg(&bias[c + 1]);
#pragma unroll
        for (int mt = 0; mt < 4; mt++) {
            int r0 = m0 + wm * 64 + mt * 16 + g;
            float2 v0, v1;
            v0.x = acc[mt][nt][0] + b0;
            v0.y = acc[mt][nt][1] + b1;
            v1.x = acc[mt][nt][2] + b0;
            v1.y = acc[mt][nt][3] + b1;
            *(float2*)&out[(size_t)r0 * OUT_F + c]       = v0;
            *(float2*)&out[(size_t)(r0 + 8) * OUT_F + c] = v1;
        }
    }
}

// ================= launch =================
extern "C" void kernel_launch(void* const* d_in, const int* in_sizes, int n_in,
                              void* d_out, int out_size) {
    const float* x    = (const float*)d_in[0];
    const float* W    = (const float*)d_in[1];
    const float* bias = (const float*)d_in[2];
    const float* lA   = (const float*)d_in[3];
    const float* lB   = (const float*)d_in[4];
    float* out = (float*)d_out;

    // k_gemm stays at launch index 3 (the ncu-captured slot)
    k_sc<<<16, 256>>>(lA, lB);
    k_ns<<<1, 256>>>();
    k_prep<<<XSPLIT_BLOCKS + (IN_F / 256) * (OUT_F / 64), 256>>>(x, W, lA, lB);

    static int smem_set = 0;
    int smem_sz = NSTG * STAGE_B;   // 98304
    if (!smem_set) {
        cudaFuncSetAttribute(k_gemm, cudaFuncAttributeMaxDynamicSharedMemorySize, smem_sz);
        smem_set = 1;
    }
    int nblocks = (TOKENS / 128) * (OUT_F / 128);   // 2048
    k_gemm<<<nblocks, 256, smem_sz>>>(bias, out);
}